// round 1
// baseline (speedup 1.0000x reference)
#include <cuda_runtime.h>
#include <cuda_bf16.h>
#include <stdint.h>
#include <math.h>

// ---------------- problem dims ----------------
#define BATCH 256
#define TSTEPS 250
#define INDIM 700
#define HDIM 256
#define ODIM 20
#define KBR 4
#define BT (BATCH * TSTEPS)   // 64000
#define INPAD 704             // 700 padded to mult of 32
#define HK 1024               // H*K
#define NR 128                // padded readout rows (20 -> 128)
#define KE1 (2 * INPAD)       // hi/lo folded K for GEMM1: 1408
#define KE2 (2 * HDIM)        // hi/lo folded K for GEMM2/3: 512

// ---------------- scratch (device globals; no runtime alloc) ----------------
__device__ __nv_bfloat16 g_Xbf[(size_t)BT * INPAD];   // 90 MB
__device__ __nv_bfloat16 g_W1s[(size_t)HK * KE1];     // [n][hi(704) | lo(704)]
__device__ __nv_bfloat16 g_W2s[(size_t)HK * KE2];     // [n][hi(256) | lo(256)]
__device__ __nv_bfloat16 g_Wrs[(size_t)NR * KE2];
__device__ float         g_C[(size_t)BT * HK];        // 262 MB, reused for C1/C2/R
__device__ __nv_bfloat16 g_S1[(size_t)BT * HDIM];     // 32 MB spikes layer1
__device__ __nv_bfloat16 g_S2[(size_t)BT * HDIM];

// ---------------- prep kernels ----------------
__global__ void prep_x_kernel(const float* __restrict__ x) {
    size_t i = (size_t)blockIdx.x * blockDim.x + threadIdx.x;
    if (i >= (size_t)BT * INPAD) return;
    int r = (int)(i / INPAD);
    int c = (int)(i % INPAD);
    float v = (c < INDIM) ? x[(size_t)r * INDIM + c] : 0.f;
    g_Xbf[i] = __float2bfloat16(v);
}

// hi/lo residual split: W = hi + lo + O(2^-17 * |W|)
__global__ void prep_w_kernel(const float* __restrict__ W, int Nin, int Npad,
                              int Kin, int Kpad, int which) {
    __nv_bfloat16* dst = (which == 0) ? g_W1s : (which == 1) ? g_W2s : g_Wrs;
    size_t total = (size_t)Npad * Kpad;
    size_t i = (size_t)blockIdx.x * blockDim.x + threadIdx.x;
    if (i >= total) return;
    int n = (int)(i / Kpad);
    int c = (int)(i % Kpad);
    float v = (n < Nin && c < Kin) ? W[(size_t)n * Kin + c] : 0.f;
    __nv_bfloat16 hi = __float2bfloat16(v);
    float lo = v - __bfloat162float(hi);
    dst[(size_t)n * (2 * Kpad) + c] = hi;
    dst[(size_t)n * (2 * Kpad) + Kpad + c] = __float2bfloat16(lo);
}

// ---------------- bf16 GEMM: C[M,N] = A[M,K'] @ B[N,K']^T, fp32 accum ----------------
// A column index folds mod FOLDK (so [X | X] virtually matches B = [Whi | Wlo]).
#define SM_STRIDE 40  // 128x32 tile rows padded to 40 halfs (80B) -> conflict-free LDS

__device__ __forceinline__ void cp16(void* sdst, const void* gsrc) {
    uint32_t s = (uint32_t)__cvta_generic_to_shared(sdst);
    asm volatile("cp.async.cg.shared.global [%0], [%1], 16;\n" :: "r"(s), "l"(gsrc));
}

template <int LDA, int FOLDK, int LDB, int LDC, int KEXT>
__device__ __forceinline__ void gemm_body(const __nv_bfloat16* __restrict__ A,
                                          const __nv_bfloat16* __restrict__ Bm,
                                          float* __restrict__ C) {
    __shared__ __nv_bfloat16 As[2][128 * SM_STRIDE];
    __shared__ __nv_bfloat16 Bs[2][128 * SM_STRIDE];

    const int m0 = blockIdx.x * 128;
    const int n0 = blockIdx.y * 128;
    const int tid = threadIdx.x;
    const int lane = tid & 31;
    const int warp = tid >> 5;
    const int wm = warp & 3;   // 4 warps along M (32 rows each)
    const int wn = warp >> 2;  // 2 warps along N (64 cols each)

    float acc[2][8][4];
#pragma unroll
    for (int i = 0; i < 2; ++i)
#pragma unroll
        for (int j = 0; j < 8; ++j)
#pragma unroll
            for (int q = 0; q < 4; ++q) acc[i][j][q] = 0.f;

    const int lrow = tid >> 2;        // 0..63
    const int lcol = (tid & 3) * 8;   // 0,8,16,24 (halfs)
    const int KT = KEXT / 32;

    // ---- issue one k-tile into stage ----
    auto issue = [&](int kt, int stage) {
        int kbase = kt * 32;
#pragma unroll
        for (int p = 0; p < 2; ++p) {
            int row = p * 64 + lrow;
            int k = kbase + lcol;
            int ka = (k >= FOLDK) ? (k - FOLDK) : k;
            cp16(&As[stage][row * SM_STRIDE + lcol], A + (size_t)(m0 + row) * LDA + ka);
        }
#pragma unroll
        for (int p = 0; p < 2; ++p) {
            int row = p * 64 + lrow;
            cp16(&Bs[stage][row * SM_STRIDE + lcol], Bm + (size_t)(n0 + row) * LDB + kbase + lcol);
        }
        asm volatile("cp.async.commit_group;\n");
    };

    issue(0, 0);

    const int r = lane >> 2;
    const int cc = (lane & 3) << 1;

    for (int kt = 0; kt < KT; ++kt) {
        if (kt + 1 < KT) {
            issue(kt + 1, (kt + 1) & 1);
            asm volatile("cp.async.wait_group 1;\n");
        } else {
            asm volatile("cp.async.wait_group 0;\n");
        }
        __syncthreads();

        const __nv_bfloat16* as = As[kt & 1];
        const __nv_bfloat16* bs = Bs[kt & 1];
#pragma unroll
        for (int ks = 0; ks < 32; ks += 16) {
            uint32_t af[2][4], bfr[8][2];
#pragma unroll
            for (int mt = 0; mt < 2; ++mt) {
                const __nv_bfloat16* pa = as + (wm * 32 + mt * 16 + r) * SM_STRIDE + ks + cc;
                af[mt][0] = *(const uint32_t*)pa;
                af[mt][1] = *(const uint32_t*)(pa + 8 * SM_STRIDE);
                af[mt][2] = *(const uint32_t*)(pa + 8);
                af[mt][3] = *(const uint32_t*)(pa + 8 * SM_STRIDE + 8);
            }
#pragma unroll
            for (int nt = 0; nt < 8; ++nt) {
                const __nv_bfloat16* pb = bs + (wn * 64 + nt * 8 + r) * SM_STRIDE + ks + cc;
                bfr[nt][0] = *(const uint32_t*)pb;
                bfr[nt][1] = *(const uint32_t*)(pb + 8);
            }
#pragma unroll
            for (int mt = 0; mt < 2; ++mt)
#pragma unroll
                for (int nt = 0; nt < 8; ++nt)
                    asm volatile(
                        "mma.sync.aligned.m16n8k16.row.col.f32.bf16.bf16.f32 "
                        "{%0,%1,%2,%3}, {%4,%5,%6,%7}, {%8,%9}, {%0,%1,%2,%3};\n"
                        : "+f"(acc[mt][nt][0]), "+f"(acc[mt][nt][1]),
                          "+f"(acc[mt][nt][2]), "+f"(acc[mt][nt][3])
                        : "r"(af[mt][0]), "r"(af[mt][1]), "r"(af[mt][2]), "r"(af[mt][3]),
                          "r"(bfr[nt][0]), "r"(bfr[nt][1]));
        }
        __syncthreads();
    }

    // epilogue
#pragma unroll
    for (int mt = 0; mt < 2; ++mt)
#pragma unroll
        for (int nt = 0; nt < 8; ++nt) {
            int row = m0 + wm * 32 + mt * 16 + r;
            int col = n0 + wn * 64 + nt * 8 + cc;
            *(float2*)(C + (size_t)row * LDC + col) = make_float2(acc[mt][nt][0], acc[mt][nt][1]);
            *(float2*)(C + (size_t)(row + 8) * LDC + col) = make_float2(acc[mt][nt][2], acc[mt][nt][3]);
        }
}

__global__ __launch_bounds__(256) void gemm1_kernel() {
    gemm_body<INPAD, INPAD, KE1, HK, KE1>(g_Xbf, g_W1s, g_C);
}
__global__ __launch_bounds__(256) void gemm2_kernel() {
    gemm_body<HDIM, HDIM, KE2, HK, KE2>(g_S1, g_W2s, g_C);
}
__global__ __launch_bounds__(256) void gemm3_kernel() {
    gemm_body<HDIM, HDIM, KE2, NR, KE2>(g_S2, g_Wrs, g_C);
}

// ---------------- time scans (elementwise recurrences) ----------------
// one thread per (b,h): 4 dendritic IIRs + LIF with subtractive reset
__global__ void scan_layer_kernel(const float* __restrict__ bias,
                                  const float* __restrict__ tau_n,
                                  const float* __restrict__ tau_m,
                                  int which) {
    const int h = threadIdx.x;  // 0..255
    const int b = blockIdx.x;   // 0..255
    __nv_bfloat16* S = which ? g_S2 : g_S1;

    float be[KBR], ob[KBR], bi[KBR];
#pragma unroll
    for (int k = 0; k < KBR; ++k) {
        float s = 1.f / (1.f + expf(-tau_n[h * KBR + k]));
        be[k] = s;
        ob[k] = 1.f - s;
        bi[k] = bias[h * KBR + k];
    }
    float al = 1.f / (1.f + expf(-tau_m[h]));
    float oa = 1.f - al;

    float d0 = 0.f, d1 = 0.f, d2 = 0.f, d3 = 0.f, m = 0.f, sp = 0.f;
    const float4* Cf = (const float4*)g_C;
    size_t base = (size_t)b * TSTEPS * (HK / 4) + h;

#pragma unroll 2
    for (int t = 0; t < TSTEPS; ++t) {
        float4 c = Cf[base + (size_t)t * (HK / 4)];
        d0 = be[0] * d0 + ob[0] * (c.x + bi[0]);
        d1 = be[1] * d1 + ob[1] * (c.y + bi[1]);
        d2 = be[2] * d2 + ob[2] * (c.z + bi[2]);
        d3 = be[3] * d3 + ob[3] * (c.w + bi[3]);
        m = al * m + oa * (d0 + d1 + d2 + d3) - sp;   // VTH=1, DT=1
        sp = (m > 1.0f) ? 1.0f : 0.0f;                 // spike(m - VTH)
        S[((size_t)b * TSTEPS + t) * HDIM + h] = __float2bfloat16(sp);
    }
}

// one thread per (b,o): leaky readout + warmup-masked mean
__global__ void scan_readout_kernel(const float* __restrict__ br,
                                    const float* __restrict__ tau_mr,
                                    const void* __restrict__ warm,
                                    float* __restrict__ out) {
    const int o = threadIdx.x;
    const int b = blockIdx.x;
    if (o >= ODIM) return;
    int w = *(const int*)warm;
    if (w < 0 || w > TSTEPS) w = (int)(*(const float*)warm);  // dtype-robust
    float al = 1.f / (1.f + expf(-tau_mr[o]));
    float oa = 1.f - al;
    float bo = br[o];
    float mr = 0.f, acc = 0.f;
    size_t base = (size_t)b * TSTEPS * NR + o;
#pragma unroll 5
    for (int t = 0; t < TSTEPS; ++t) {
        float v = g_C[base + (size_t)t * NR];
        mr = al * mr + oa * (v + bo);
        if (t >= w) acc += mr;
    }
    out[b * ODIM + o] = acc / (float)(TSTEPS - w);
}

// ---------------- launch ----------------
extern "C" void kernel_launch(void* const* d_in, const int* in_sizes, int n_in,
                              void* d_out, int out_size) {
    const float* x      = (const float*)d_in[0];
    const float* W1     = (const float*)d_in[1];
    const float* b1     = (const float*)d_in[2];
    const float* tau_n1 = (const float*)d_in[3];
    const float* tau_m1 = (const float*)d_in[4];
    const float* W2     = (const float*)d_in[5];
    const float* b2     = (const float*)d_in[6];
    const float* tau_n2 = (const float*)d_in[7];
    const float* tau_m2 = (const float*)d_in[8];
    const float* Wr     = (const float*)d_in[9];
    const float* br     = (const float*)d_in[10];
    const float* tau_mr = (const float*)d_in[11];
    const void*  warm   = d_in[12];
    float* out = (float*)d_out;

    // prep: bf16 inputs + hi/lo weight splits (deterministic, every call)
    prep_x_kernel<<<(int)(((size_t)BT * INPAD + 255) / 256), 256>>>(x);
    prep_w_kernel<<<(HK * INPAD + 255) / 256, 256>>>(W1, HK, HK, INDIM, INPAD, 0);
    prep_w_kernel<<<(HK * HDIM + 255) / 256, 256>>>(W2, HK, HK, HDIM, HDIM, 1);
    prep_w_kernel<<<(NR * HDIM + 255) / 256, 256>>>(Wr, ODIM, NR, HDIM, HDIM, 2);

    dim3 gBig(BT / 128, HK / 128);  // (500, 8)
    dim3 gSml(BT / 128, 1);         // (500, 1)

    gemm1_kernel<<<gBig, 256>>>();
    scan_layer_kernel<<<BATCH, HDIM>>>(b1, tau_n1, tau_m1, 0);
    gemm2_kernel<<<gBig, 256>>>();
    scan_layer_kernel<<<BATCH, HDIM>>>(b2, tau_n2, tau_m2, 1);
    gemm3_kernel<<<gSml, 256>>>();
    scan_readout_kernel<<<BATCH, 32>>>(br, tau_mr, warm, out);
}